// round 10
// baseline (speedup 1.0000x reference)
#include <cuda_runtime.h>
#include <math.h>

// Problem constants (fixed by reference setup_inputs)
#define SN      10
#define ITERS   100
#define WARMUP  4
#define HWPIX   (128*128)
#define LOG2E   1.4426950408889634f
#define LN2     0.6931471805599453f

// Global accumulators: [0]=n_neg [1]=n_pos [2]=sumsq_neg [3]=sumsq_posneg [4]=loss_pos
// Zero at load; last finishing block resets them, preserving the invariant across replays.
__device__ double g_acc[5] = {0, 0, 0, 0, 0};
__device__ unsigned int g_ticket = 0;

// ---- packed f32x2 helpers (Blackwell sm_100+) ----
__device__ __forceinline__ unsigned long long f2_mul(unsigned long long a, unsigned long long b) {
    unsigned long long d;
    asm("mul.rn.f32x2 %0, %1, %2;" : "=l"(d) : "l"(a), "l"(b));
    return d;
}
__device__ __forceinline__ unsigned long long f2_fma(unsigned long long a, unsigned long long b, unsigned long long c) {
    unsigned long long d;
    asm("fma.rn.f32x2 %0, %1, %2, %3;" : "=l"(d) : "l"(a), "l"(b), "l"(c));
    return d;
}
__device__ __forceinline__ unsigned long long f2_add(unsigned long long a, unsigned long long b) {
    unsigned long long d;
    asm("add.rn.f32x2 %0, %1, %2;" : "=l"(d) : "l"(a), "l"(b));
    return d;
}
__device__ __forceinline__ unsigned long long f2_pack(float lo, float hi) {
    unsigned long long d;
    asm("mov.b64 %0, {%1, %2};" : "=l"(d) : "f"(lo), "f"(hi));
    return d;
}
__device__ __forceinline__ void f2_unpack(unsigned long long v, float& lo, float& hi) {
    asm("mov.b64 {%0, %1}, %2;" : "=f"(lo), "=f"(hi) : "l"(v));
}
__device__ __forceinline__ float frcp(float x) {
    float y; asm("rcp.approx.f32 %0, %1;" : "=f"(y) : "f"(x)); return y;
}
__device__ __forceinline__ float fex2(float x) {
    float y; asm("ex2.approx.f32 %0, %1;" : "=f"(y) : "f"(x)); return y;
}

// 4 CTAs/SM (128-reg cap). Safe this time because the cold state (oys/oxs) is
// explicitly parked in shared memory: the loop-carried live set is only
// K2(50)+beta(10)+alpha(10)+misc(~15) ~= 85 regs, so the cap produces no
// hot-loop spills (unlike R5, which kept everything in registers).
__global__ __launch_bounds__(128, 4) void ol_main_kernel(
    const float* __restrict__ outp_g,
    const float* __restrict__ tgt_g,
    const float* __restrict__ msk_g,
    float* __restrict__ result,
    int npix)
{
    // offsets pre-scaled by log2(e); [m][tid] -> conflict-free per-thread access
    __shared__ float s_oy[SN][128];
    __shared__ float s_ox[SN][128];

    const int tid = threadIdx.x;
    int p = blockIdx.x * blockDim.x + tid;

    float negf = 0.f, posf = 0.f, sumsq = 0.f, pnsq = 0.f, lp = 0.f;

    if (p < npix) {
        const int b  = p >> 14;            // HWPIX = 16384
        const int hw = p & (HWPIX - 1);
        const int h  = hw >> 7;
        const int w  = hw & 127;

        const float* outp = outp_g + (size_t)b * 36 * HWPIX + hw;
        const float* tgtp = tgt_g  + (size_t)b * 20 * HWPIX + hw;
        const float* mskp = msk_g  + (size_t)b * 10 * HWPIX + hw;

        // ---- pos/neg from mask ----
        float msum = 0.f;
        #pragma unroll
        for (int s = 0; s < SN; s++) msum += mskp[s * HWPIX];
        posf = (msum >= 1.0f) ? 1.0f : 0.0f;
        negf = 1.0f - posf;

        // ---- offsets (scaled by log2(e)); registers die at loop entry,
        //      smem copy serves the epilogue ----
        float oys[SN], oxs[SN];
        #pragma unroll
        for (int m = 0; m < 18; m++) {
            const int head  = (m >= 9) ? 1 : 0;
            const int local = m - head * 9;
            const int i = local / 3;
            const int j = local - i * 3;
            const int cy = head * 18 + local;        // d=0
            const float vy = outp[cy * HWPIX];
            const float vx = outp[(cy + 9) * HWPIX]; // d=1
            sumsq += vy * vy + vx * vx;
            const float oyv = vy + (float)(i - 1) + (float)h;
            const float oxv = vx + (float)(j - 1) + (float)w;
            if (m < SN) {
                oys[m] = oyv * LOG2E; oxs[m] = oxv * LOG2E;
                s_oy[m][tid] = oys[m]; s_ox[m][tid] = oxs[m];
            } else {
                pnsq += oyv * oyv + oxv * oxv;
            }
        }

        // ---- Gibbs kernel K[s][m] = 2^(rmin - c2[s][m]) (row max = 1), packed over m ----
        unsigned long long K2[SN][5];
        #pragma unroll
        for (int s = 0; s < SN; s++) {
            const float tys = tgtp[s * HWPIX] * LOG2E;
            const float txs = tgtp[(SN + s) * HWPIX] * LOG2E;
            float c[SN];
            float rm = 3.4e38f;
            #pragma unroll
            for (int m = 0; m < SN; m++) {
                c[m] = fabsf(tys - oys[m]) + fabsf(txs - oxs[m]);
                rm = fminf(rm, c[m]);
            }
            #pragma unroll
            for (int k = 0; k < 5; k++)
                K2[s][k] = f2_pack(fex2(rm - c[2 * k]), fex2(rm - c[2 * k + 1]));
        }

        // ---- Sinkhorn, rescaled: fixed point alpha.(K beta) = 1, beta.(K^T alpha) = 1.
        //      WARMUP exact-rcp iterations enter the Newton basin, then division-free
        //      Newton-coupled scaling (0 MUFU / iteration). ----
        float alpha[SN];
        unsigned long long beta[5];
        #pragma unroll
        for (int k = 0; k < 5; k++) beta[k] = f2_pack(20.0f, 20.0f);  // v0 = 0

        #pragma unroll
        for (int wu = 0; wu < WARMUP; wu++) {
            #pragma unroll
            for (int s = 0; s < SN; s++) {
                unsigned long long t0 = f2_mul(K2[s][0], beta[0]);
                unsigned long long t1 = f2_mul(K2[s][1], beta[1]);
                t0 = f2_fma(K2[s][2], beta[2], t0);
                t1 = f2_fma(K2[s][3], beta[3], t1);
                t0 = f2_fma(K2[s][4], beta[4], t0);
                float lo, hi; f2_unpack(f2_add(t0, t1), lo, hi);
                alpha[s] = frcp(lo + hi);
            }
            unsigned long long e0[5], e1[5];
            {
                const unsigned long long a0 = f2_pack(alpha[0], alpha[0]);
                const unsigned long long a5 = f2_pack(alpha[5], alpha[5]);
                #pragma unroll
                for (int k = 0; k < 5; k++) {
                    e0[k] = f2_mul(K2[0][k], a0);
                    e1[k] = f2_mul(K2[5][k], a5);
                }
            }
            #pragma unroll
            for (int s = 1; s < 5; s++) {
                const unsigned long long aa = f2_pack(alpha[s], alpha[s]);
                const unsigned long long bb = f2_pack(alpha[s + 5], alpha[s + 5]);
                #pragma unroll
                for (int k = 0; k < 5; k++) {
                    e0[k] = f2_fma(K2[s][k], aa, e0[k]);
                    e1[k] = f2_fma(K2[s + 5][k], bb, e1[k]);
                }
            }
            #pragma unroll
            for (int k = 0; k < 5; k++) {
                float lo, hi; f2_unpack(f2_add(e0[k], e1[k]), lo, hi);
                beta[k] = f2_pack(frcp(lo), frcp(hi));
            }
        }

        // Newton-mode main loop. Convergence is read off the Newton factor itself:
        // f = 2 - d*alpha, and |f - 1| = |1 - d*alpha| is the fixed-point residual.
        int it = 0;
        while (true) {
            bool conv = true;
            #pragma unroll
            for (int s = 0; s < SN; s++) {
                unsigned long long t0 = f2_mul(K2[s][0], beta[0]);
                unsigned long long t1 = f2_mul(K2[s][1], beta[1]);
                t0 = f2_fma(K2[s][2], beta[2], t0);
                t1 = f2_fma(K2[s][3], beta[3], t1);
                t0 = f2_fma(K2[s][4], beta[4], t0);
                float lo, hi; f2_unpack(f2_add(t0, t1), lo, hi);
                const float d = lo + hi;
                const float f = fmaf(-d, alpha[s], 2.0f);   // Newton factor
                conv = conv && (fabsf(f - 1.0f) <= 1e-4f);
                alpha[s] *= f;
            }
            unsigned long long e0[5], e1[5];
            {
                const unsigned long long a0 = f2_pack(alpha[0], alpha[0]);
                const unsigned long long a5 = f2_pack(alpha[5], alpha[5]);
                #pragma unroll
                for (int k = 0; k < 5; k++) {
                    e0[k] = f2_mul(K2[0][k], a0);
                    e1[k] = f2_mul(K2[5][k], a5);
                }
            }
            #pragma unroll
            for (int s = 1; s < 5; s++) {
                const unsigned long long aa = f2_pack(alpha[s], alpha[s]);
                const unsigned long long bb = f2_pack(alpha[s + 5], alpha[s + 5]);
                #pragma unroll
                for (int k = 0; k < 5; k++) {
                    e0[k] = f2_fma(K2[s][k], aa, e0[k]);
                    e1[k] = f2_fma(K2[s + 5][k], bb, e1[k]);
                }
            }
            #pragma unroll
            for (int k = 0; k < 5; k++) {
                float lo, hi; f2_unpack(f2_add(e0[k], e1[k]), lo, hi);
                float b0, b1; f2_unpack(beta[k], b0, b1);
                b0 = b0 * fmaf(-lo, b0, 2.0f);   // Newton rcp step for beta
                b1 = b1 * fmaf(-hi, b1, 2.0f);
                beta[k] = f2_pack(b0, b1);
            }
            if (++it >= ITERS) break;
            if (__all_sync(__activemask(), conv)) break;
        }

        // ---- loss_pos = sum_s mask_s * alpha_s * sum_m K[s][m]*beta_m*cost[s][m]
        //      (offsets read back from smem; costs in log2 units, one LN2 rescale) ----
        #pragma unroll
        for (int s = 0; s < SN; s++) {
            const float tys = tgtp[s * HWPIX] * LOG2E;
            const float txs = tgtp[(SN + s) * HWPIX] * LOG2E;
            unsigned long long acc = 0ull;   // packed (0,0)
            #pragma unroll
            for (int k = 0; k < 5; k++) {
                const float c0 = fabsf(tys - s_oy[2 * k][tid])     + fabsf(txs - s_ox[2 * k][tid]);
                const float c1 = fabsf(tys - s_oy[2 * k + 1][tid]) + fabsf(txs - s_ox[2 * k + 1][tid]);
                acc = f2_fma(f2_mul(K2[s][k], beta[k]), f2_pack(c0, c1), acc);
            }
            float lo, hi; f2_unpack(acc, lo, hi);
            const float ms = mskp[s * HWPIX];  // reload (L2 hit)
            lp = fmaf(ms * alpha[s], lo + hi, lp);
        }
        lp *= LN2;
        sumsq *= negf;
        pnsq  *= posf;
    }

    // ---- warp reduce 5 quantities, one double atomic per warp each ----
    float vals[5] = { negf, posf, sumsq, pnsq, lp };
    #pragma unroll
    for (int k = 0; k < 5; k++) {
        float v = vals[k];
        #pragma unroll
        for (int off = 16; off; off >>= 1)
            v += __shfl_xor_sync(0xffffffffu, v, off);
        if ((tid & 31) == 0)
            atomicAdd(&g_acc[k], (double)v);
    }

    // ---- fused finalize: last block computes the scalar result and resets state ----
    __syncthreads();
    if (tid == 0) {
        __threadfence();
        const unsigned t = atomicAdd(&g_ticket, 1u);
        if (t == gridDim.x - 1) {
            __threadfence();
            const double n_neg = g_acc[0];
            const double n_pos = g_acc[1];
            const double loss_neg     = sqrt(g_acc[2]) / n_neg;
            const double loss_pos_neg = sqrt(g_acc[3]) / n_pos;
            result[0] = (float)((loss_neg + loss_pos_neg) * 100.0
                                + g_acc[4] / (n_pos + 0.0001));
            #pragma unroll
            for (int k = 0; k < 5; k++) g_acc[k] = 0.0;
            __threadfence();
            g_ticket = 0u;
        }
    }
}

extern "C" void kernel_launch(void* const* d_in, const int* in_sizes, int n_in,
                              void* d_out, int out_size) {
    const float* out_t  = (const float*)d_in[0];   // (B, 36, 128, 128)
    const float* target = (const float*)d_in[1];   // (B, 20, 128, 128)
    const float* mask   = (const float*)d_in[2];   // (B, 10, 128, 128)

    const int npix = in_sizes[2] / SN;             // B * H * W
    const int threads = 128;
    const int blocks = (npix + threads - 1) / threads;

    ol_main_kernel<<<blocks, threads>>>(out_t, target, mask, (float*)d_out, npix);
}

// round 11
// speedup vs baseline: 1.1926x; 1.1926x over previous
#include <cuda_runtime.h>
#include <math.h>

// Problem constants (fixed by reference setup_inputs)
#define SN      10
#define ITERS   100
#define WARMUP  4
#define HWPIX   (128*128)
#define LOG2E   1.4426950408889634f
#define LN2     0.6931471805599453f

// Global accumulators: [k*16] for k in 0..4 -> each on its own 128B line so the
// five atomic streams hit different LTS slices instead of serializing on one.
// [0]=n_neg [1]=n_pos [2]=sumsq_neg [3]=sumsq_posneg [4]=loss_pos
__device__ double g_acc[5 * 16] = {0};
__device__ unsigned int g_ticket = 0;

// ---- packed f32x2 helpers (Blackwell sm_100+) ----
__device__ __forceinline__ unsigned long long f2_mul(unsigned long long a, unsigned long long b) {
    unsigned long long d;
    asm("mul.rn.f32x2 %0, %1, %2;" : "=l"(d) : "l"(a), "l"(b));
    return d;
}
__device__ __forceinline__ unsigned long long f2_fma(unsigned long long a, unsigned long long b, unsigned long long c) {
    unsigned long long d;
    asm("fma.rn.f32x2 %0, %1, %2, %3;" : "=l"(d) : "l"(a), "l"(b), "l"(c));
    return d;
}
__device__ __forceinline__ unsigned long long f2_add(unsigned long long a, unsigned long long b) {
    unsigned long long d;
    asm("add.rn.f32x2 %0, %1, %2;" : "=l"(d) : "l"(a), "l"(b));
    return d;
}
__device__ __forceinline__ unsigned long long f2_pack(float lo, float hi) {
    unsigned long long d;
    asm("mov.b64 %0, {%1, %2};" : "=l"(d) : "f"(lo), "f"(hi));
    return d;
}
__device__ __forceinline__ void f2_unpack(unsigned long long v, float& lo, float& hi) {
    asm("mov.b64 {%0, %1}, %2;" : "=f"(lo), "=f"(hi) : "l"(v));
}
__device__ __forceinline__ float frcp(float x) {
    float y; asm("rcp.approx.f32 %0, %1;" : "=f"(y) : "f"(x)); return y;
}
__device__ __forceinline__ float fex2(float x) {
    float y; asm("ex2.approx.f32 %0, %1;" : "=f"(y) : "f"(x)); return y;
}

// R8 configuration (best so far): 3 CTAs/SM, everything register-resident.
__global__ __launch_bounds__(128, 3) void ol_main_kernel(
    const float* __restrict__ outp_g,
    const float* __restrict__ tgt_g,
    const float* __restrict__ msk_g,
    float* __restrict__ result,
    int npix)
{
    __shared__ float s_part[5][4];   // per-warp partials for the block reduction

    const int tid = threadIdx.x;
    int p = blockIdx.x * blockDim.x + tid;

    float negf = 0.f, posf = 0.f, sumsq = 0.f, pnsq = 0.f, lp = 0.f;

    if (p < npix) {
        const int b  = p >> 14;            // HWPIX = 16384
        const int hw = p & (HWPIX - 1);
        const int h  = hw >> 7;
        const int w  = hw & 127;

        const float* outp = outp_g + (size_t)b * 36 * HWPIX + hw;
        const float* tgtp = tgt_g  + (size_t)b * 20 * HWPIX + hw;
        const float* mskp = msk_g  + (size_t)b * 10 * HWPIX + hw;

        // ---- pos/neg from mask ----
        float msum = 0.f;
        #pragma unroll
        for (int s = 0; s < SN; s++) msum += mskp[s * HWPIX];
        posf = (msum >= 1.0f) ? 1.0f : 0.0f;
        negf = 1.0f - posf;

        // ---- offsets (stored pre-scaled by log2(e) for ex2-domain costs) ----
        float oys[SN], oxs[SN];
        #pragma unroll
        for (int m = 0; m < 18; m++) {
            const int head  = (m >= 9) ? 1 : 0;
            const int local = m - head * 9;
            const int i = local / 3;
            const int j = local - i * 3;
            const int cy = head * 18 + local;        // d=0
            const float vy = outp[cy * HWPIX];
            const float vx = outp[(cy + 9) * HWPIX]; // d=1
            sumsq += vy * vy + vx * vx;
            const float oyv = vy + (float)(i - 1) + (float)h;
            const float oxv = vx + (float)(j - 1) + (float)w;
            if (m < SN) { oys[m] = oyv * LOG2E; oxs[m] = oxv * LOG2E; }
            else        { pnsq += oyv * oyv + oxv * oxv; }
        }

        // ---- Gibbs kernel K[s][m] = 2^(rmin - c2[s][m]) (row max = 1), packed over m ----
        unsigned long long K2[SN][5];
        #pragma unroll
        for (int s = 0; s < SN; s++) {
            const float tys = tgtp[s * HWPIX] * LOG2E;
            const float txs = tgtp[(SN + s) * HWPIX] * LOG2E;
            float c[SN];
            float rm = 3.4e38f;
            #pragma unroll
            for (int m = 0; m < SN; m++) {
                c[m] = fabsf(tys - oys[m]) + fabsf(txs - oxs[m]);
                rm = fminf(rm, c[m]);
            }
            #pragma unroll
            for (int k = 0; k < 5; k++)
                K2[s][k] = f2_pack(fex2(rm - c[2 * k]), fex2(rm - c[2 * k + 1]));
        }

        // ---- Sinkhorn, rescaled: fixed point alpha.(K beta) = 1, beta.(K^T alpha) = 1.
        //      WARMUP exact-rcp iterations enter the Newton basin, then division-free
        //      Newton-coupled scaling (0 MUFU / iteration). ----
        float alpha[SN];
        unsigned long long beta[5];
        #pragma unroll
        for (int k = 0; k < 5; k++) beta[k] = f2_pack(20.0f, 20.0f);  // v0 = 0

        #pragma unroll
        for (int wu = 0; wu < WARMUP; wu++) {
            #pragma unroll
            for (int s = 0; s < SN; s++) {
                unsigned long long t0 = f2_mul(K2[s][0], beta[0]);
                unsigned long long t1 = f2_mul(K2[s][1], beta[1]);
                t0 = f2_fma(K2[s][2], beta[2], t0);
                t1 = f2_fma(K2[s][3], beta[3], t1);
                t0 = f2_fma(K2[s][4], beta[4], t0);
                float lo, hi; f2_unpack(f2_add(t0, t1), lo, hi);
                alpha[s] = frcp(lo + hi);
            }
            unsigned long long e0[5], e1[5];
            {
                const unsigned long long a0 = f2_pack(alpha[0], alpha[0]);
                const unsigned long long a5 = f2_pack(alpha[5], alpha[5]);
                #pragma unroll
                for (int k = 0; k < 5; k++) {
                    e0[k] = f2_mul(K2[0][k], a0);
                    e1[k] = f2_mul(K2[5][k], a5);
                }
            }
            #pragma unroll
            for (int s = 1; s < 5; s++) {
                const unsigned long long aa = f2_pack(alpha[s], alpha[s]);
                const unsigned long long bb = f2_pack(alpha[s + 5], alpha[s + 5]);
                #pragma unroll
                for (int k = 0; k < 5; k++) {
                    e0[k] = f2_fma(K2[s][k], aa, e0[k]);
                    e1[k] = f2_fma(K2[s + 5][k], bb, e1[k]);
                }
            }
            #pragma unroll
            for (int k = 0; k < 5; k++) {
                float lo, hi; f2_unpack(f2_add(e0[k], e1[k]), lo, hi);
                beta[k] = f2_pack(frcp(lo), frcp(hi));
            }
        }

        // Newton-mode main loop; residual read off the Newton factor (|f-1| = |1 - d*alpha|).
        int it = 0;
        while (true) {
            bool conv = true;
            #pragma unroll
            for (int s = 0; s < SN; s++) {
                unsigned long long t0 = f2_mul(K2[s][0], beta[0]);
                unsigned long long t1 = f2_mul(K2[s][1], beta[1]);
                t0 = f2_fma(K2[s][2], beta[2], t0);
                t1 = f2_fma(K2[s][3], beta[3], t1);
                t0 = f2_fma(K2[s][4], beta[4], t0);
                float lo, hi; f2_unpack(f2_add(t0, t1), lo, hi);
                const float d = lo + hi;
                const float f = fmaf(-d, alpha[s], 2.0f);   // Newton factor
                conv = conv && (fabsf(f - 1.0f) <= 1e-4f);
                alpha[s] *= f;
            }
            unsigned long long e0[5], e1[5];
            {
                const unsigned long long a0 = f2_pack(alpha[0], alpha[0]);
                const unsigned long long a5 = f2_pack(alpha[5], alpha[5]);
                #pragma unroll
                for (int k = 0; k < 5; k++) {
                    e0[k] = f2_mul(K2[0][k], a0);
                    e1[k] = f2_mul(K2[5][k], a5);
                }
            }
            #pragma unroll
            for (int s = 1; s < 5; s++) {
                const unsigned long long aa = f2_pack(alpha[s], alpha[s]);
                const unsigned long long bb = f2_pack(alpha[s + 5], alpha[s + 5]);
                #pragma unroll
                for (int k = 0; k < 5; k++) {
                    e0[k] = f2_fma(K2[s][k], aa, e0[k]);
                    e1[k] = f2_fma(K2[s + 5][k], bb, e1[k]);
                }
            }
            #pragma unroll
            for (int k = 0; k < 5; k++) {
                float lo, hi; f2_unpack(f2_add(e0[k], e1[k]), lo, hi);
                float b0, b1; f2_unpack(beta[k], b0, b1);
                b0 = b0 * fmaf(-lo, b0, 2.0f);   // Newton rcp step for beta
                b1 = b1 * fmaf(-hi, b1, 2.0f);
                beta[k] = f2_pack(b0, b1);
            }
            if (++it >= ITERS) break;
            if (__all_sync(__activemask(), conv)) break;
        }

        // ---- loss_pos = sum_s mask_s * alpha_s * sum_m K[s][m]*beta_m*cost[s][m] ----
        #pragma unroll
        for (int s = 0; s < SN; s++) {
            const float tys = tgtp[s * HWPIX] * LOG2E;
            const float txs = tgtp[(SN + s) * HWPIX] * LOG2E;
            unsigned long long acc = 0ull;   // packed (0,0)
            #pragma unroll
            for (int k = 0; k < 5; k++) {
                const float c0 = fabsf(tys - oys[2 * k])     + fabsf(txs - oxs[2 * k]);
                const float c1 = fabsf(tys - oys[2 * k + 1]) + fabsf(txs - oxs[2 * k + 1]);
                acc = f2_fma(f2_mul(K2[s][k], beta[k]), f2_pack(c0, c1), acc);
            }
            float lo, hi; f2_unpack(acc, lo, hi);
            const float ms = mskp[s * HWPIX];  // reload (L2 hit)
            lp = fmaf(ms * alpha[s], lo + hi, lp);
        }
        lp *= LN2;
        sumsq *= negf;
        pnsq  *= posf;
    }

    // ---- hierarchical reduction: warp shuffle -> smem -> ONE thread's atomics.
    //      Cuts the global f64 atomic count 4x (8192 warps -> 2048 blocks) and,
    //      with the 128B-padded accumulators, removes the single-line LTS
    //      serialization that capped every kernel since R4 at ~75us. ----
    float vals[5] = { negf, posf, sumsq, pnsq, lp };
    const int wid = tid >> 5;
    const int lid = tid & 31;
    #pragma unroll
    for (int k = 0; k < 5; k++) {
        float v = vals[k];
        #pragma unroll
        for (int off = 16; off; off >>= 1)
            v += __shfl_xor_sync(0xffffffffu, v, off);
        if (lid == 0) s_part[k][wid] = v;
    }
    __syncthreads();
    if (tid < 5) {
        const float bsum = s_part[tid][0] + s_part[tid][1]
                         + s_part[tid][2] + s_part[tid][3];
        atomicAdd(&g_acc[tid * 16], (double)bsum);
    }

    // ---- fused finalize: last block computes the scalar result and resets state ----
    __syncthreads();
    if (tid == 0) {
        __threadfence();
        const unsigned t = atomicAdd(&g_ticket, 1u);
        if (t == gridDim.x - 1) {
            __threadfence();
            const double n_neg = g_acc[0 * 16];
            const double n_pos = g_acc[1 * 16];
            const double loss_neg     = sqrt(g_acc[2 * 16]) / n_neg;
            const double loss_pos_neg = sqrt(g_acc[3 * 16]) / n_pos;
            result[0] = (float)((loss_neg + loss_pos_neg) * 100.0
                                + g_acc[4 * 16] / (n_pos + 0.0001));
            #pragma unroll
            for (int k = 0; k < 5; k++) g_acc[k * 16] = 0.0;
            __threadfence();
            g_ticket = 0u;
        }
    }
}

extern "C" void kernel_launch(void* const* d_in, const int* in_sizes, int n_in,
                              void* d_out, int out_size) {
    const float* out_t  = (const float*)d_in[0];   // (B, 36, 128, 128)
    const float* target = (const float*)d_in[1];   // (B, 20, 128, 128)
    const float* mask   = (const float*)d_in[2];   // (B, 10, 128, 128)

    const int npix = in_sizes[2] / SN;             // B * H * W
    const int threads = 128;
    const int blocks = (npix + threads - 1) / threads;

    ol_main_kernel<<<blocks, threads>>>(out_t, target, mask, (float*)d_out, npix);
}

// round 12
// speedup vs baseline: 1.2320x; 1.0331x over previous
#include <cuda_runtime.h>
#include <math.h>

// Problem constants (fixed by reference setup_inputs)
#define SN      10
#define ITERS   100
#define WARMUP  4
#define HWPIX   (128*128)
#define LOG2E   1.4426950408889634f
#define LN2     0.6931471805599453f

// Global accumulators: [k*16] for k in 0..4 -> each on its own 128B line so the
// five atomic streams hit different LTS slices instead of serializing on one.
// [0]=n_neg [1]=n_pos [2]=sumsq_neg [3]=sumsq_posneg [4]=loss_pos
__device__ double g_acc[5 * 16] = {0};
__device__ unsigned int g_ticket = 0;

// ---- packed f32x2 helpers (Blackwell sm_100+) ----
__device__ __forceinline__ unsigned long long f2_mul(unsigned long long a, unsigned long long b) {
    unsigned long long d;
    asm("mul.rn.f32x2 %0, %1, %2;" : "=l"(d) : "l"(a), "l"(b));
    return d;
}
__device__ __forceinline__ unsigned long long f2_fma(unsigned long long a, unsigned long long b, unsigned long long c) {
    unsigned long long d;
    asm("fma.rn.f32x2 %0, %1, %2, %3;" : "=l"(d) : "l"(a), "l"(b), "l"(c));
    return d;
}
__device__ __forceinline__ unsigned long long f2_add(unsigned long long a, unsigned long long b) {
    unsigned long long d;
    asm("add.rn.f32x2 %0, %1, %2;" : "=l"(d) : "l"(a), "l"(b));
    return d;
}
__device__ __forceinline__ unsigned long long f2_pack(float lo, float hi) {
    unsigned long long d;
    asm("mov.b64 %0, {%1, %2};" : "=l"(d) : "f"(lo), "f"(hi));
    return d;
}
__device__ __forceinline__ void f2_unpack(unsigned long long v, float& lo, float& hi) {
    asm("mov.b64 {%0, %1}, %2;" : "=f"(lo), "=f"(hi) : "l"(v));
}
__device__ __forceinline__ float frcp(float x) {
    float y; asm("rcp.approx.f32 %0, %1;" : "=f"(y) : "f"(x)); return y;
}
__device__ __forceinline__ float fex2(float x) {
    float y; asm("ex2.approx.f32 %0, %1;" : "=f"(y) : "f"(x)); return y;
}

// 4 CTAs/SM (128-reg cap), made safe by parking the cold offsets (oys/oxs,
// used only in setup + epilogue) in shared memory. This is the R9 register
// diet re-tested WITHOUT the LTS atomic floor that contaminated R9's result.
__global__ __launch_bounds__(128, 4) void ol_main_kernel(
    const float* __restrict__ outp_g,
    const float* __restrict__ tgt_g,
    const float* __restrict__ msk_g,
    float* __restrict__ result,
    int npix)
{
    __shared__ float s_oy[SN][128];   // offsets pre-scaled by log2(e), [m][tid]
    __shared__ float s_ox[SN][128];
    __shared__ float s_part[5][4];    // per-warp partials for the block reduction

    const int tid = threadIdx.x;
    int p = blockIdx.x * blockDim.x + tid;

    float negf = 0.f, posf = 0.f, sumsq = 0.f, pnsq = 0.f, lp = 0.f;

    if (p < npix) {
        const int b  = p >> 14;            // HWPIX = 16384
        const int hw = p & (HWPIX - 1);
        const int h  = hw >> 7;
        const int w  = hw & 127;

        const float* outp = outp_g + (size_t)b * 36 * HWPIX + hw;
        const float* tgtp = tgt_g  + (size_t)b * 20 * HWPIX + hw;
        const float* mskp = msk_g  + (size_t)b * 10 * HWPIX + hw;

        // ---- pos/neg from mask ----
        float msum = 0.f;
        #pragma unroll
        for (int s = 0; s < SN; s++) msum += mskp[s * HWPIX];
        posf = (msum >= 1.0f) ? 1.0f : 0.0f;
        negf = 1.0f - posf;

        // ---- offsets (scaled by log2(e)); register copies die at loop entry,
        //      smem copy serves the epilogue so they are not loop-carried ----
        float oys[SN], oxs[SN];
        #pragma unroll
        for (int m = 0; m < 18; m++) {
            const int head  = (m >= 9) ? 1 : 0;
            const int local = m - head * 9;
            const int i = local / 3;
            const int j = local - i * 3;
            const int cy = head * 18 + local;        // d=0
            const float vy = outp[cy * HWPIX];
            const float vx = outp[(cy + 9) * HWPIX]; // d=1
            sumsq += vy * vy + vx * vx;
            const float oyv = vy + (float)(i - 1) + (float)h;
            const float oxv = vx + (float)(j - 1) + (float)w;
            if (m < SN) {
                oys[m] = oyv * LOG2E; oxs[m] = oxv * LOG2E;
                s_oy[m][tid] = oys[m]; s_ox[m][tid] = oxs[m];
            } else {
                pnsq += oyv * oyv + oxv * oxv;
            }
        }

        // ---- Gibbs kernel K[s][m] = 2^(rmin - c2[s][m]) (row max = 1), packed over m ----
        unsigned long long K2[SN][5];
        #pragma unroll
        for (int s = 0; s < SN; s++) {
            const float tys = tgtp[s * HWPIX] * LOG2E;
            const float txs = tgtp[(SN + s) * HWPIX] * LOG2E;
            float c[SN];
            float rm = 3.4e38f;
            #pragma unroll
            for (int m = 0; m < SN; m++) {
                c[m] = fabsf(tys - oys[m]) + fabsf(txs - oxs[m]);
                rm = fminf(rm, c[m]);
            }
            #pragma unroll
            for (int k = 0; k < 5; k++)
                K2[s][k] = f2_pack(fex2(rm - c[2 * k]), fex2(rm - c[2 * k + 1]));
        }

        // ---- Sinkhorn, rescaled: fixed point alpha.(K beta) = 1, beta.(K^T alpha) = 1.
        //      WARMUP exact-rcp iterations enter the Newton basin, then division-free
        //      Newton-coupled scaling (0 MUFU / iteration). ----
        float alpha[SN];
        unsigned long long beta[5];
        #pragma unroll
        for (int k = 0; k < 5; k++) beta[k] = f2_pack(20.0f, 20.0f);  // v0 = 0

        #pragma unroll
        for (int wu = 0; wu < WARMUP; wu++) {
            #pragma unroll
            for (int s = 0; s < SN; s++) {
                unsigned long long t0 = f2_mul(K2[s][0], beta[0]);
                unsigned long long t1 = f2_mul(K2[s][1], beta[1]);
                t0 = f2_fma(K2[s][2], beta[2], t0);
                t1 = f2_fma(K2[s][3], beta[3], t1);
                t0 = f2_fma(K2[s][4], beta[4], t0);
                float lo, hi; f2_unpack(f2_add(t0, t1), lo, hi);
                alpha[s] = frcp(lo + hi);
            }
            unsigned long long e0[5], e1[5];
            {
                const unsigned long long a0 = f2_pack(alpha[0], alpha[0]);
                const unsigned long long a5 = f2_pack(alpha[5], alpha[5]);
                #pragma unroll
                for (int k = 0; k < 5; k++) {
                    e0[k] = f2_mul(K2[0][k], a0);
                    e1[k] = f2_mul(K2[5][k], a5);
                }
            }
            #pragma unroll
            for (int s = 1; s < 5; s++) {
                const unsigned long long aa = f2_pack(alpha[s], alpha[s]);
                const unsigned long long bb = f2_pack(alpha[s + 5], alpha[s + 5]);
                #pragma unroll
                for (int k = 0; k < 5; k++) {
                    e0[k] = f2_fma(K2[s][k], aa, e0[k]);
                    e1[k] = f2_fma(K2[s + 5][k], bb, e1[k]);
                }
            }
            #pragma unroll
            for (int k = 0; k < 5; k++) {
                float lo, hi; f2_unpack(f2_add(e0[k], e1[k]), lo, hi);
                beta[k] = f2_pack(frcp(lo), frcp(hi));
            }
        }

        // Newton-mode main loop; residual read off the Newton factor (|f-1| = |1 - d*alpha|).
        int it = 0;
        while (true) {
            bool conv = true;
            #pragma unroll
            for (int s = 0; s < SN; s++) {
                unsigned long long t0 = f2_mul(K2[s][0], beta[0]);
                unsigned long long t1 = f2_mul(K2[s][1], beta[1]);
                t0 = f2_fma(K2[s][2], beta[2], t0);
                t1 = f2_fma(K2[s][3], beta[3], t1);
                t0 = f2_fma(K2[s][4], beta[4], t0);
                float lo, hi; f2_unpack(f2_add(t0, t1), lo, hi);
                const float d = lo + hi;
                const float f = fmaf(-d, alpha[s], 2.0f);   // Newton factor
                conv = conv && (fabsf(f - 1.0f) <= 1e-4f);
                alpha[s] *= f;
            }
            unsigned long long e0[5], e1[5];
            {
                const unsigned long long a0 = f2_pack(alpha[0], alpha[0]);
                const unsigned long long a5 = f2_pack(alpha[5], alpha[5]);
                #pragma unroll
                for (int k = 0; k < 5; k++) {
                    e0[k] = f2_mul(K2[0][k], a0);
                    e1[k] = f2_mul(K2[5][k], a5);
                }
            }
            #pragma unroll
            for (int s = 1; s < 5; s++) {
                const unsigned long long aa = f2_pack(alpha[s], alpha[s]);
                const unsigned long long bb = f2_pack(alpha[s + 5], alpha[s + 5]);
                #pragma unroll
                for (int k = 0; k < 5; k++) {
                    e0[k] = f2_fma(K2[s][k], aa, e0[k]);
                    e1[k] = f2_fma(K2[s + 5][k], bb, e1[k]);
                }
            }
            #pragma unroll
            for (int k = 0; k < 5; k++) {
                float lo, hi; f2_unpack(f2_add(e0[k], e1[k]), lo, hi);
                float b0, b1; f2_unpack(beta[k], b0, b1);
                b0 = b0 * fmaf(-lo, b0, 2.0f);   // Newton rcp step for beta
                b1 = b1 * fmaf(-hi, b1, 2.0f);
                beta[k] = f2_pack(b0, b1);
            }
            if (++it >= ITERS) break;
            if (__all_sync(__activemask(), conv)) break;
        }

        // ---- loss_pos = sum_s mask_s * alpha_s * sum_m K[s][m]*beta_m*cost[s][m]
        //      (offsets read back from smem; costs in log2 units, one LN2 rescale) ----
        #pragma unroll
        for (int s = 0; s < SN; s++) {
            const float tys = tgtp[s * HWPIX] * LOG2E;
            const float txs = tgtp[(SN + s) * HWPIX] * LOG2E;
            unsigned long long acc = 0ull;   // packed (0,0)
            #pragma unroll
            for (int k = 0; k < 5; k++) {
                const float c0 = fabsf(tys - s_oy[2 * k][tid])     + fabsf(txs - s_ox[2 * k][tid]);
                const float c1 = fabsf(tys - s_oy[2 * k + 1][tid]) + fabsf(txs - s_ox[2 * k + 1][tid]);
                acc = f2_fma(f2_mul(K2[s][k], beta[k]), f2_pack(c0, c1), acc);
            }
            float lo, hi; f2_unpack(acc, lo, hi);
            const float ms = mskp[s * HWPIX];  // reload (L2 hit)
            lp = fmaf(ms * alpha[s], lo + hi, lp);
        }
        lp *= LN2;
        sumsq *= negf;
        pnsq  *= posf;
    }

    // ---- hierarchical reduction: warp shuffle -> smem -> ONE thread's atomics
    //      onto 128B-padded accumulators (proven 8us win in R10) ----
    float vals[5] = { negf, posf, sumsq, pnsq, lp };
    const int wid = tid >> 5;
    const int lid = tid & 31;
    #pragma unroll
    for (int k = 0; k < 5; k++) {
        float v = vals[k];
        #pragma unroll
        for (int off = 16; off; off >>= 1)
            v += __shfl_xor_sync(0xffffffffu, v, off);
        if (lid == 0) s_part[k][wid] = v;
    }
    __syncthreads();
    if (tid < 5) {
        const float bsum = s_part[tid][0] + s_part[tid][1]
                         + s_part[tid][2] + s_part[tid][3];
        atomicAdd(&g_acc[tid * 16], (double)bsum);
    }

    // ---- fused finalize: last block computes the scalar result and resets state ----
    __syncthreads();
    if (tid == 0) {
        __threadfence();
        const unsigned t = atomicAdd(&g_ticket, 1u);
        if (t == gridDim.x - 1) {
            __threadfence();
            const double n_neg = g_acc[0 * 16];
            const double n_pos = g_acc[1 * 16];
            const double loss_neg     = sqrt(g_acc[2 * 16]) / n_neg;
            const double loss_pos_neg = sqrt(g_acc[3 * 16]) / n_pos;
            result[0] = (float)((loss_neg + loss_pos_neg) * 100.0
                                + g_acc[4 * 16] / (n_pos + 0.0001));
            #pragma unroll
            for (int k = 0; k < 5; k++) g_acc[k * 16] = 0.0;
            __threadfence();
            g_ticket = 0u;
        }
    }
}

extern "C" void kernel_launch(void* const* d_in, const int* in_sizes, int n_in,
                              void* d_out, int out_size) {
    const float* out_t  = (const float*)d_in[0];   // (B, 36, 128, 128)
    const float* target = (const float*)d_in[1];   // (B, 20, 128, 128)
    const float* mask   = (const float*)d_in[2];   // (B, 10, 128, 128)

    const int npix = in_sizes[2] / SN;             // B * H * W
    const int threads = 128;
    const int blocks = (npix + threads - 1) / threads;

    ol_main_kernel<<<blocks, threads>>>(out_t, target, mask, (float*)d_out, npix);
}